// round 4
// baseline (speedup 1.0000x reference)
#include <cuda_runtime.h>

#define T_STEPS 32
#define BATCH   8
#define NT      256
#define CIN_    1024
#define DCH     512
#define KC      64
#define PIX     196

// ---------------- scratch (device globals; no allocations) ----------------
__device__ float g_xr[NT * DCH * PIX];       // (n, d, p)
__device__ float g_wxb[NT * KC * PIX];       // (n, k, p)
__device__ float g_h[2 * BATCH * KC * PIX];  // per-direction hidden state
__device__ float g_z[2 * BATCH * KC * PIX];
__device__ float g_rh[2 * BATCH * KC * PIX];
__device__ float g_fwd[NT * KC * PIX];
__device__ float g_bwd[NT * KC * PIX];
__device__ float g_assign[NT * KC * PIX];
__device__ float g_asum[NT * KC];
__device__ float g_vlad[BATCH * KC * DCH];

static __device__ __forceinline__ float sigf(float v) { return 1.0f / (1.0f + expf(-v)); }

// ---------------- init: zero hidden states + vlad accumulator ----------------
__global__ void init_kernel()
{
    int i = blockIdx.x * 256 + threadIdx.x;
    if (i < 2 * BATCH * KC * PIX) g_h[i] = 0.0f;
    if (i < BATCH * KC * DCH)     g_vlad[i] = 0.0f;
}

// ---------------- 1x1 conv as tiled SGEMM ----------------
// out[(n*OC + d)*196 + p] = bias[d] + sum_c W[d][c] * X[(n*CIN + c)*196 + p]
// Columns = global pixel index (n,p). 50176 columns total; BN divides exactly.
template<int BM, int BN, int TM, int TN, int CIN, int OC>
__global__ void conv1x1_kernel(const float* __restrict__ X,
                               const float* __restrict__ W,
                               const float* __restrict__ bias,
                               float* __restrict__ out)
{
    const int BK = 8;
    __shared__ float As[BK][BM];
    __shared__ float Bs[BK][BN];
    __shared__ int cbase[BN];
    __shared__ int obase[BN];

    const int tid = threadIdx.x;           // 256 threads
    for (int j = tid; j < BN; j += 256) {
        int jg = blockIdx.x * BN + j;
        int n = jg / PIX;
        int p = jg - n * PIX;
        cbase[j] = n * CIN * PIX + p;
        obase[j] = n * OC * PIX + p;
    }
    __syncthreads();

    const int m0 = blockIdx.y * BM;
    const int tx = tid & 15, ty = tid >> 4;

    float acc[TM][TN];
#pragma unroll
    for (int i = 0; i < TM; i++)
#pragma unroll
        for (int j = 0; j < TN; j++) acc[i][j] = 0.0f;

    for (int k0 = 0; k0 < CIN; k0 += BK) {
        // A tile: BM x 8, loaded as float4 along c
        for (int i = tid; i < BM * 2; i += 256) {
            int m  = i >> 1;
            int cg = (i & 1) * 4;
            const float4 w4 = *(const float4*)&W[(m0 + m) * CIN + k0 + cg];
            As[cg + 0][m] = w4.x; As[cg + 1][m] = w4.y;
            As[cg + 2][m] = w4.z; As[cg + 3][m] = w4.w;
        }
        // B tile: 8 x BN, coalesced over pixels
        for (int i = tid; i < BK * BN; i += 256) {
            int k = i / BN, j = i - k * BN;
            Bs[k][j] = X[cbase[j] + (k0 + k) * PIX];
        }
        __syncthreads();
#pragma unroll
        for (int kk = 0; kk < BK; kk++) {
            float a[TM], b[TN];
#pragma unroll
            for (int i = 0; i < TM; i++) a[i] = As[kk][ty * TM + i];
#pragma unroll
            for (int j = 0; j < TN; j++) b[j] = Bs[kk][tx * TN + j];
#pragma unroll
            for (int i = 0; i < TM; i++)
#pragma unroll
                for (int j = 0; j < TN; j++) acc[i][j] += a[i] * b[j];
        }
        __syncthreads();
    }

#pragma unroll
    for (int i = 0; i < TM; i++) {
        int d = m0 + ty * TM + i;
        float bv = bias[d];
#pragma unroll
        for (int j = 0; j < TN; j++) {
            int jj = tx * TN + j;
            out[obase[jj] + d * PIX] = acc[i][j] + bv;
        }
    }
}

// ---------------- GRU step kernel A: z, r gates + r*h ----------------
// grid: (8 ko-groups, 8 batch, 2 dir); block: 224 threads
// smem: h padded 64 x 16 x (17-stride) + Uz/Ur slices for 8 out channels
__global__ void gru_a_kernel(int s, const float* __restrict__ Uz, const float* __restrict__ Ur)
{
    extern __shared__ float sm[];
    float* hs  = sm;                 // 64*272
    float* wzs = sm + 64 * 272;      // 4608
    float* wrs = wzs + 4608;         // 4608

    const int dir = blockIdx.z, b = blockIdx.y, kg = blockIdx.x;
    const int t = (dir == 0) ? s : (31 - s);
    const int n = b * 32 + t;
    const int tid = threadIdx.x;
    const float* hsrc = g_h + (dir * BATCH + b) * KC * PIX;

    for (int i = tid; i < KC * 256; i += 224) {
        int ci = i >> 8, yy = (i >> 4) & 15, xx = i & 15;
        int y = yy - 1, x = xx - 1;
        float v = 0.0f;
        if ((unsigned)y < 14u && (unsigned)x < 14u) v = hsrc[ci * PIX + y * 14 + x];
        hs[ci * 272 + yy * 17 + xx] = v;
    }
    const int ko0 = kg * 8;
    for (int i = tid; i < 8 * 64 * 9; i += 224) {
        wzs[i] = Uz[ko0 * 576 + i];
        wrs[i] = Ur[ko0 * 576 + i];
    }
    __syncthreads();

    const int ko_l = tid / 28, grp = tid - ko_l * 28;
    const int row = grp >> 1, xh = (grp & 1) * 7;
    const int ko = ko0 + ko_l;

    float az[7], ar[7];
#pragma unroll
    for (int i = 0; i < 7; i++) { az[i] = 0.0f; ar[i] = 0.0f; }

    const float* wzb = wzs + ko_l * 576;
    const float* wrb = wrs + ko_l * 576;
    const float* hb  = hs + row * 17 + xh;

#pragma unroll 1
    for (int ci = 0; ci < 64; ci++) {
        const float* hp = hb + ci * 272;
        float r0[9], r1[9], r2[9];
#pragma unroll
        for (int i = 0; i < 9; i++) { r0[i] = hp[i]; r1[i] = hp[17 + i]; r2[i] = hp[34 + i]; }
        const float* wz9 = wzb + ci * 9;
        const float* wr9 = wrb + ci * 9;
        float z0=wz9[0],z1=wz9[1],z2=wz9[2],z3=wz9[3],z4=wz9[4],z5=wz9[5],z6=wz9[6],z7=wz9[7],z8=wz9[8];
        float q0=wr9[0],q1=wr9[1],q2=wr9[2],q3=wr9[3],q4=wr9[4],q5=wr9[5],q6=wr9[6],q7=wr9[7],q8=wr9[8];
#pragma unroll
        for (int px = 0; px < 7; px++) {
            az[px] += z0*r0[px] + z1*r0[px+1] + z2*r0[px+2]
                    + z3*r1[px] + z4*r1[px+1] + z5*r1[px+2]
                    + z6*r2[px] + z7*r2[px+1] + z8*r2[px+2];
            ar[px] += q0*r0[px] + q1*r0[px+1] + q2*r0[px+2]
                    + q3*r1[px] + q4*r1[px+1] + q5*r1[px+2]
                    + q6*r2[px] + q7*r2[px+1] + q8*r2[px+2];
        }
    }

    const int pbase = row * 14 + xh;
    const float* wt  = g_wxb + (n * KC + ko) * PIX + pbase;
    float* zz = g_z  + ((dir * BATCH + b) * KC + ko) * PIX + pbase;
    float* rh = g_rh + ((dir * BATCH + b) * KC + ko) * PIX + pbase;
    const float* hko = hs + ko * 272 + (row + 1) * 17 + (xh + 1);
#pragma unroll
    for (int px = 0; px < 7; px++) {
        float w = wt[px];
        float z = sigf(w + az[px]);
        float r = sigf(w + ar[px]);
        zz[px] = z;
        rh[px] = r * hko[px];
    }
}

// ---------------- GRU step kernel B: h~ conv + state update ----------------
__global__ void gru_b_kernel(int s, const float* __restrict__ Uh)
{
    extern __shared__ float sm[];
    float* hs  = sm;                 // 64*272 (holds r*h image)
    float* whs = sm + 64 * 272;      // 4608

    const int dir = blockIdx.z, b = blockIdx.y, kg = blockIdx.x;
    const int t = (dir == 0) ? s : (31 - s);
    const int n = b * 32 + t;
    const int tid = threadIdx.x;
    const float* rsrc = g_rh + (dir * BATCH + b) * KC * PIX;

    for (int i = tid; i < KC * 256; i += 224) {
        int ci = i >> 8, yy = (i >> 4) & 15, xx = i & 15;
        int y = yy - 1, x = xx - 1;
        float v = 0.0f;
        if ((unsigned)y < 14u && (unsigned)x < 14u) v = rsrc[ci * PIX + y * 14 + x];
        hs[ci * 272 + yy * 17 + xx] = v;
    }
    const int ko0 = kg * 8;
    for (int i = tid; i < 8 * 64 * 9; i += 224) whs[i] = Uh[ko0 * 576 + i];
    __syncthreads();

    const int ko_l = tid / 28, grp = tid - ko_l * 28;
    const int row = grp >> 1, xh = (grp & 1) * 7;
    const int ko = ko0 + ko_l;

    float ah[7];
#pragma unroll
    for (int i = 0; i < 7; i++) ah[i] = 0.0f;

    const float* whb = whs + ko_l * 576;
    const float* hb  = hs + row * 17 + xh;

#pragma unroll 1
    for (int ci = 0; ci < 64; ci++) {
        const float* hp = hb + ci * 272;
        float r0[9], r1[9], r2[9];
#pragma unroll
        for (int i = 0; i < 9; i++) { r0[i] = hp[i]; r1[i] = hp[17 + i]; r2[i] = hp[34 + i]; }
        const float* w9 = whb + ci * 9;
        float w0=w9[0],w1=w9[1],w2=w9[2],w3=w9[3],w4=w9[4],w5=w9[5],w6=w9[6],w7=w9[7],w8=w9[8];
#pragma unroll
        for (int px = 0; px < 7; px++) {
            ah[px] += w0*r0[px] + w1*r0[px+1] + w2*r0[px+2]
                    + w3*r1[px] + w4*r1[px+1] + w5*r1[px+2]
                    + w6*r2[px] + w7*r2[px+1] + w8*r2[px+2];
        }
    }

    const int pbase = row * 14 + xh;
    const int base  = ((dir * BATCH + b) * KC + ko) * PIX + pbase;
    const float* wt = g_wxb + (n * KC + ko) * PIX + pbase;
    const float* zz = g_z + base;
    float* hst = g_h + base;
    float* gout = ((dir == 0) ? g_fwd : g_bwd) + (n * KC + ko) * PIX + pbase;
#pragma unroll
    for (int px = 0; px < 7; px++) {
        float hold = hst[px];
        float z = zz[px];
        float hh = tanhf(wt[px] + ah[px]);
        float hn = (1.0f - z) * hh + z * hold;
        hst[px] = hn;
        gout[px] = hn;
    }
}

// ---------------- softmax over K per pixel + per-(n,k) pixel sums ----------------
__global__ void softmax_kernel()
{
    const int n = blockIdx.x;
    const int p = threadIdx.x;   // 224 threads, 196 active
    const bool act = p < PIX;
    __shared__ float asum_s[KC];
    if (p < KC) asum_s[p] = 0.0f;
    __syncthreads();

    const float* f  = g_fwd + n * KC * PIX + p;
    const float* bd = g_bwd + n * KC * PIX + p;
    float m = -1e30f;
    if (act) {
        for (int k = 0; k < KC; k++) m = fmaxf(m, f[k * PIX] + bd[k * PIX]);
    }
    float ssum = 0.0f;
    if (act) {
        for (int k = 0; k < KC; k++) ssum += expf(f[k * PIX] + bd[k * PIX] - m);
    }
    const float inv = act ? (1.0f / ssum) : 0.0f;
    float* A = g_assign + n * KC * PIX + p;
    for (int k = 0; k < KC; k++) {
        float e = act ? expf(f[k * PIX] + bd[k * PIX] - m) * inv : 0.0f;
        if (act) A[k * PIX] = e;
        float es = e;
#pragma unroll
        for (int off = 16; off; off >>= 1) es += __shfl_down_sync(0xffffffffu, es, off);
        if ((p & 31) == 0) atomicAdd(&asum_s[k], es);
    }
    __syncthreads();
    if (p < KC) g_asum[n * KC + p] = asum_s[p];
}

// ---------------- VLAD einsum: vlad[b,k,d] += sum_{t,p} assign * xr ----------------
// grid: (8 d-tiles, 8 b, 8 t-chunks of 4 frames); 256 threads; fp32 atomics reduce chunks
__global__ void vlad_gemm_kernel()
{
    __shared__ float As[14][65];
    __shared__ float Bs[14][65];
    const int b = blockIdx.y, d0 = blockIdx.x * 64, ch = blockIdx.z;
    const int tid = threadIdx.x;
    const int tx = tid & 15, ty = tid >> 4;

    float acc[4][4];
#pragma unroll
    for (int i = 0; i < 4; i++)
#pragma unroll
        for (int j = 0; j < 4; j++) acc[i][j] = 0.0f;

    for (int f = 0; f < 4; f++) {
        int n = b * 32 + ch * 4 + f;
        const float* Ap = g_assign + n * KC * PIX;
        const float* Xp = g_xr + n * DCH * PIX;
        for (int p0 = 0; p0 < PIX; p0 += 14) {
            for (int i = tid; i < 896; i += 256) {
                int r = i / 14, pp = i - r * 14;
                As[pp][r] = Ap[r * PIX + p0 + pp];
                Bs[pp][r] = Xp[(d0 + r) * PIX + p0 + pp];
            }
            __syncthreads();
#pragma unroll
            for (int pp = 0; pp < 14; pp++) {
                float a[4], x[4];
#pragma unroll
                for (int i = 0; i < 4; i++) a[i] = As[pp][ty * 4 + i];
#pragma unroll
                for (int j = 0; j < 4; j++) x[j] = Bs[pp][tx * 4 + j];
#pragma unroll
                for (int i = 0; i < 4; i++)
#pragma unroll
                    for (int j = 0; j < 4; j++) acc[i][j] += a[i] * x[j];
            }
            __syncthreads();
        }
    }
#pragma unroll
    for (int i = 0; i < 4; i++)
#pragma unroll
        for (int j = 0; j < 4; j++)
            atomicAdd(&g_vlad[(b * KC + ty * 4 + i) * DCH + d0 + tx * 4 + j], acc[i][j]);
}

// ---------------- subtract a-term + intra-row L2 normalize ----------------
__global__ void rownorm_kernel(const float* __restrict__ centers, float* __restrict__ out)
{
    const int k = blockIdx.x, b = blockIdx.y;
    const int tid = threadIdx.x;  // 128
    __shared__ float sred[128];
    __shared__ float s_sh;

    if (tid < 32) {
        float s = g_asum[(b * 32 + tid) * KC + k];
#pragma unroll
        for (int off = 16; off; off >>= 1) s += __shfl_down_sync(0xffffffffu, s, off);
        if (tid == 0) s_sh = s;
    }
    __syncthreads();
    const float s = s_sh;

    float v[4];
    float ssq = 0.0f;
#pragma unroll
    for (int j = 0; j < 4; j++) {
        int d = j * 128 + tid;
        v[j] = g_vlad[(b * KC + k) * DCH + d] - s * centers[k * DCH + d];
        ssq += v[j] * v[j];
    }
    sred[tid] = ssq;
    __syncthreads();
    for (int off = 64; off; off >>= 1) {
        if (tid < off) sred[tid] += sred[tid + off];
        __syncthreads();
    }
    const float scale = 1.0f / fmaxf(sqrtf(sred[0]), 1e-12f);
#pragma unroll
    for (int j = 0; j < 4; j++)
        out[b * KC * DCH + k * DCH + j * 128 + tid] = v[j] * scale;
}

// ---------------- final per-batch L2 normalize ----------------
__global__ void bnorm_kernel(float* __restrict__ out)
{
    const int b = blockIdx.x;
    const int tid = threadIdx.x; // 256
    __shared__ float sred[256];
    float* o = out + b * KC * DCH;
    float ssq = 0.0f;
    for (int i = tid; i < KC * DCH; i += 256) { float v = o[i]; ssq += v * v; }
    sred[tid] = ssq;
    __syncthreads();
    for (int off = 128; off; off >>= 1) {
        if (tid < off) sred[tid] += sred[tid + off];
        __syncthreads();
    }
    const float scale = 1.0f / fmaxf(sqrtf(sred[0]), 1e-12f);
    for (int i = tid; i < KC * DCH; i += 256) o[i] *= scale;
}

// ---------------- host launcher ----------------
extern "C" void kernel_launch(void* const* d_in, const int* in_sizes, int n_in,
                              void* d_out, int out_size)
{
    const float* x       = (const float*)d_in[0];
    const float* redu_w  = (const float*)d_in[1];
    const float* redu_b  = (const float*)d_in[2];
    const float* share_w = (const float*)d_in[3];
    const float* share_b = (const float*)d_in[4];
    const float* U_z     = (const float*)d_in[5];
    const float* U_r     = (const float*)d_in[6];
    const float* U_h     = (const float*)d_in[7];
    const float* centers = (const float*)d_in[8];
    float* out = (float*)d_out;

    const int SMEM_A = (64 * 272 + 2 * 4608) * 4;   // 104 KB
    const int SMEM_B = (64 * 272 + 4608) * 4;       // 86 KB
    cudaFuncSetAttribute(gru_a_kernel, cudaFuncAttributeMaxDynamicSharedMemorySize, SMEM_A);
    cudaFuncSetAttribute(gru_b_kernel, cudaFuncAttributeMaxDynamicSharedMemorySize, SMEM_B);

    void* xr_p;  cudaGetSymbolAddress(&xr_p,  g_xr);
    void* wxb_p; cudaGetSymbolAddress(&wxb_p, g_wxb);

    init_kernel<<<1024, 256>>>();

    // xr = 1x1 reduce conv + bias : GEMM (512 x 1024) @ (1024 x 50176)
    conv1x1_kernel<128, 128, 8, 8, CIN_, DCH>
        <<<dim3(50176 / 128, DCH / 128), 256>>>(x, redu_w, redu_b, (float*)xr_p);

    // wxb = 1x1 share conv + bias : GEMM (64 x 512) @ (512 x 50176)
    conv1x1_kernel<64, 128, 4, 8, DCH, KC>
        <<<dim3(50176 / 128, 1), 256>>>((const float*)xr_p, share_w, share_b, (float*)wxb_p);

    // bidirectional GRU: 32 steps, both directions fused per launch
    for (int s = 0; s < T_STEPS; s++) {
        gru_a_kernel<<<dim3(8, BATCH, 2), 224, SMEM_A>>>(s, U_z, U_r);
        gru_b_kernel<<<dim3(8, BATCH, 2), 224, SMEM_B>>>(s, U_h);
    }

    softmax_kernel<<<NT, 224>>>();
    vlad_gemm_kernel<<<dim3(8, BATCH, 8), 256>>>();
    rownorm_kernel<<<dim3(KC, BATCH), 128>>>(centers, out);
    bnorm_kernel<<<BATCH, 256>>>(out);
}

// round 5
// speedup vs baseline: 1.6408x; 1.6408x over previous
#include <cuda_runtime.h>

#define T_STEPS 32
#define BATCH   8
#define NT      256
#define CIN_    1024
#define DCH     512
#define KC      64
#define PIX     196

// ---------------- scratch (device globals; no allocations) ----------------
__device__ float g_xr[NT * DCH * PIX];       // (n, d, p)
__device__ float g_wxb[NT * KC * PIX];       // (n, k, p)
__device__ float g_h[2 * BATCH * KC * PIX];  // per-direction hidden state
__device__ float g_rh[2 * BATCH * KC * PIX];
__device__ float g_fwd[NT * KC * PIX];
__device__ float g_bwd[NT * KC * PIX];
__device__ float g_assign[NT * KC * PIX];
__device__ float g_asum[NT * KC];
__device__ float g_vlad[BATCH * KC * DCH];
__device__ unsigned int g_barrier[16];

static __device__ __forceinline__ float sigf(float v) { return 1.0f / (1.0f + expf(-v)); }

// packed fp32x2 helpers (Blackwell f32x2 pipe; ptxas won't auto-fuse)
static __device__ __forceinline__ unsigned long long pack2(float v) {
    unsigned long long r;
    unsigned u = __float_as_uint(v);
    asm("mov.b64 %0, {%1, %1};" : "=l"(r) : "r"(u));
    return r;
}
static __device__ __forceinline__ void ffma2(unsigned long long& d,
                                             unsigned long long a,
                                             unsigned long long b) {
    asm volatile("fma.rn.f32x2 %0, %1, %2, %0;" : "+l"(d) : "l"(a), "l"(b));
}

// ---------------- init: zero hidden states + vlad + barriers ----------------
__global__ void init_kernel()
{
    int i = blockIdx.x * 256 + threadIdx.x;
    if (i < 2 * BATCH * KC * PIX) g_h[i] = 0.0f;
    if (i < BATCH * KC * DCH)     g_vlad[i] = 0.0f;
    if (i < 16)                   g_barrier[i] = 0u;
}

// ---------------- 1x1 conv as double-buffered tiled SGEMM (f32x2 FMAs) ----------------
// out[(n*OC + d)*196 + p] = bias[d] + sum_c W[d][c] * X[(n*CIN + c)*196 + p]
template<int BM, int TM, int CIN, int OC>
__global__ void __launch_bounds__(256)
conv1x1_db(const float* __restrict__ X, const float* __restrict__ W,
           const float* __restrict__ bias, float* __restrict__ out)
{
    constexpr int BK = 16, BN = 128, TN = 8;
    constexpr int AL4 = (BM * BK) / (4 * 256);   // float4 A loads per thread
    __shared__ __align__(16) float As[2][BK][BM];
    __shared__ __align__(16) float Bs[2][BK][BN];
    __shared__ int cbase[BN], obase[BN];

    const int tid = threadIdx.x;
    if (tid < BN) {
        int jg = blockIdx.x * BN + tid;
        int n = jg / PIX, p = jg - n * PIX;
        cbase[tid] = n * CIN * PIX + p;
        obase[tid] = n * OC * PIX + p;
    }
    __syncthreads();

    const int m0 = blockIdx.y * BM;
    const int tx = tid & 15, ty = tid >> 4;
    const int bj = tid & 127, bk = tid >> 7;   // B loader: pixel col, k-half
    const int cb = cbase[bj];

    float4 areg[AL4];
    float  breg[8];

    auto loadA = [&](int k0) {
#pragma unroll
        for (int i = 0; i < AL4; i++) {
            int idx = tid + i * 256;
            int r = idx >> 2, c4 = idx & 3;
            areg[i] = *(const float4*)&W[(m0 + r) * CIN + k0 + c4 * 4];
        }
    };
    auto loadB = [&](int k0) {
#pragma unroll
        for (int i = 0; i < 8; i++) breg[i] = X[cb + (k0 + bk * 8 + i) * PIX];
    };
    auto storeA = [&](int buf) {
#pragma unroll
        for (int i = 0; i < AL4; i++) {
            int idx = tid + i * 256;
            int r = idx >> 2, c4 = idx & 3;
            As[buf][c4 * 4 + 0][r] = areg[i].x;
            As[buf][c4 * 4 + 1][r] = areg[i].y;
            As[buf][c4 * 4 + 2][r] = areg[i].z;
            As[buf][c4 * 4 + 3][r] = areg[i].w;
        }
    };
    auto storeB = [&](int buf) {
#pragma unroll
        for (int i = 0; i < 8; i++) Bs[buf][bk * 8 + i][bj] = breg[i];
    };

    unsigned long long acc2[TM / 2][TN];
#pragma unroll
    for (int i = 0; i < TM / 2; i++)
#pragma unroll
        for (int j = 0; j < TN; j++) acc2[i][j] = 0ull;

    loadA(0); loadB(0);
    storeA(0); storeB(0);
    __syncthreads();

    int buf = 0;
    for (int k0 = 0; k0 < CIN; k0 += BK) {
        const bool more = (k0 + BK) < CIN;
        if (more) { loadA(k0 + BK); loadB(k0 + BK); }
#pragma unroll
        for (int kk = 0; kk < BK; kk++) {
            unsigned long long a2[TM / 2];
#pragma unroll
            for (int i = 0; i < TM / 2; i += 2) {
                ulonglong2 av = *(const ulonglong2*)&As[buf][kk][ty * TM + i * 2];
                a2[i] = av.x; a2[i + 1] = av.y;
            }
            float4 b0 = *(const float4*)&Bs[buf][kk][tx * TN];
            float4 b1 = *(const float4*)&Bs[buf][kk][tx * TN + 4];
            unsigned long long bb[8];
            bb[0] = pack2(b0.x); bb[1] = pack2(b0.y); bb[2] = pack2(b0.z); bb[3] = pack2(b0.w);
            bb[4] = pack2(b1.x); bb[5] = pack2(b1.y); bb[6] = pack2(b1.z); bb[7] = pack2(b1.w);
#pragma unroll
            for (int i = 0; i < TM / 2; i++)
#pragma unroll
                for (int j = 0; j < TN; j++) ffma2(acc2[i][j], a2[i], bb[j]);
        }
        if (more) {
            storeA(buf ^ 1); storeB(buf ^ 1);
            __syncthreads();
            buf ^= 1;
        }
    }

#pragma unroll
    for (int i = 0; i < TM / 2; i++) {
        int d0 = m0 + ty * TM + 2 * i;
        float bv0 = bias[d0], bv1 = bias[d0 + 1];
#pragma unroll
        for (int j = 0; j < TN; j++) {
            unsigned long long u = acc2[i][j];
            float lo = __uint_as_float((unsigned)u);
            float hi = __uint_as_float((unsigned)(u >> 32));
            int o = obase[tx * TN + j];
            out[o + d0 * PIX]       = lo + bv0;
            out[o + (d0 + 1) * PIX] = hi + bv1;
        }
    }
}

// ---------------- persistent bidirectional GRU ----------------
// grid: 128 blocks = 16 groups (dir*8+b) x 8 kg. All co-resident (1 block/SM).
// Each block: 448 threads = 2 ci-halves x 8 ko x 28 pixel-groups (7 px each).
// Weights live in SMEM for all 32 steps; h / r*h pass through L2 (__ldcg reads,
// write-through stores) with spin barriers among the 8 blocks of a group.
#define GRU_THREADS 448
#define HS_FLOATS   (64 * 272)
#define WS_FLOATS   4608
#define PP_FLOATS   1568
#define GRU_SMEM_FLOATS (HS_FLOATS + 3 * WS_FLOATS + 2 * PP_FLOATS)

__global__ void __launch_bounds__(GRU_THREADS, 1)
gru_persistent(const float* __restrict__ Uz, const float* __restrict__ Ur,
               const float* __restrict__ Uh)
{
    extern __shared__ float sm[];
    float* hs = sm;                          // 64 x 272 padded image
    float* wz = sm + HS_FLOATS;
    float* wr = wz + WS_FLOATS;
    float* wh = wr + WS_FLOATS;
    float* p0 = wh + WS_FLOATS;              // partials gate 0 / hcand
    float* p1 = p0 + PP_FLOATS;              // partials gate 1

    const int blk = blockIdx.x;
    const int grp = blk >> 3;                // dir*8 + b
    const int kg  = blk & 7;
    const int dir = grp >> 3;
    const int b   = grp & 7;
    const int tid = threadIdx.x;

    const int ko0 = kg * 8;
    for (int i = tid; i < WS_FLOATS; i += GRU_THREADS) {
        wz[i] = Uz[ko0 * 576 + i];
        wr[i] = Ur[ko0 * 576 + i];
        wh[i] = Uh[ko0 * 576 + i];
    }
    for (int i = tid; i < HS_FLOATS; i += GRU_THREADS) hs[i] = 0.0f;  // borders stay 0

    const int half  = tid / 224;             // ci-half: 0 or 1
    const int lt    = tid - half * 224;
    const int ko_l  = lt / 28;
    const int g28   = lt - ko_l * 28;
    const int row   = g28 >> 1, xh = (g28 & 1) * 7;
    const int ko    = ko0 + ko_l;
    const int ci0   = half * 32;
    const int pbase = row * 14 + xh;
    const int pidx  = ko_l * PIX + pbase;

    float* hstate = g_h  + grp * KC * PIX;
    float* rhbuf  = g_rh + grp * KC * PIX;
    float* gdst   = (dir == 0) ? g_fwd : g_bwd;

    unsigned bar_target = 0;
    float zreg[7], hold[7];

    for (int s = 0; s < T_STEPS; s++) {
        const int t = dir ? (31 - s) : s;
        const int n = b * 32 + t;
        const float* wt = g_wxb + (n * KC + ko) * PIX + pbase;

        // ---- stage h (interior only) ----
        for (int i = tid; i < KC * PIX; i += GRU_THREADS) {
            int ci = i / PIX, p = i - ci * PIX;
            int y = p / 14, x = p - y * 14;
            hs[ci * 272 + (y + 1) * 17 + (x + 1)] = __ldcg(&hstate[i]);
        }
        __syncthreads();

        // ---- phase A: z,r convs over this half's 32 channels ----
        float az[7], ar[7];
#pragma unroll
        for (int i = 0; i < 7; i++) { az[i] = 0.0f; ar[i] = 0.0f; }
        {
            const float* wzb = wz + ko_l * 576 + ci0 * 9;
            const float* wrb = wr + ko_l * 576 + ci0 * 9;
            const float* hb  = hs + ci0 * 272 + row * 17 + xh;
#pragma unroll 1
            for (int ci = 0; ci < 32; ci++) {
                const float* hp = hb + ci * 272;
                float r0[9], r1[9], r2[9];
#pragma unroll
                for (int i = 0; i < 9; i++) { r0[i] = hp[i]; r1[i] = hp[17 + i]; r2[i] = hp[34 + i]; }
                const float* wz9 = wzb + ci * 9;
                const float* wr9 = wrb + ci * 9;
                float z0=wz9[0],z1=wz9[1],z2=wz9[2],z3=wz9[3],z4=wz9[4],z5=wz9[5],z6=wz9[6],z7=wz9[7],z8=wz9[8];
                float q0=wr9[0],q1=wr9[1],q2=wr9[2],q3=wr9[3],q4=wr9[4],q5=wr9[5],q6=wr9[6],q7=wr9[7],q8=wr9[8];
#pragma unroll
                for (int px = 0; px < 7; px++) {
                    az[px] += z0*r0[px] + z1*r0[px+1] + z2*r0[px+2]
                            + z3*r1[px] + z4*r1[px+1] + z5*r1[px+2]
                            + z6*r2[px] + z7*r2[px+1] + z8*r2[px+2];
                    ar[px] += q0*r0[px] + q1*r0[px+1] + q2*r0[px+2]
                            + q3*r1[px] + q4*r1[px+1] + q5*r1[px+2]
                            + q6*r2[px] + q7*r2[px+1] + q8*r2[px+2];
                }
            }
        }
        if (half == 1) {
#pragma unroll
            for (int px = 0; px < 7; px++) { p0[pidx + px] = az[px]; p1[pidx + px] = ar[px]; }
        }
        __syncthreads();
        if (half == 0) {
            const float* hko = hs + ko * 272 + (row + 1) * 17 + (xh + 1);
#pragma unroll
            for (int px = 0; px < 7; px++) {
                float w = wt[px];
                float z = sigf(w + az[px] + p0[pidx + px]);
                float r = sigf(w + ar[px] + p1[pidx + px]);
                float h0 = hko[px];
                zreg[px] = z;
                hold[px] = h0;
                rhbuf[ko * PIX + pbase + px] = r * h0;
            }
        }

        // ---- group barrier #1 ----
        __threadfence();
        __syncthreads();
        bar_target += 8;
        if (tid == 0) {
            atomicAdd(&g_barrier[grp], 1u);
            while (*((volatile unsigned int*)&g_barrier[grp]) < bar_target) __nanosleep(64);
            __threadfence();
        }
        __syncthreads();

        // ---- stage r*h ----
        for (int i = tid; i < KC * PIX; i += GRU_THREADS) {
            int ci = i / PIX, p = i - ci * PIX;
            int y = p / 14, x = p - y * 14;
            hs[ci * 272 + (y + 1) * 17 + (x + 1)] = __ldcg(&rhbuf[i]);
        }
        __syncthreads();

        // ---- phase B: h-candidate conv ----
        float ah[7];
#pragma unroll
        for (int i = 0; i < 7; i++) ah[i] = 0.0f;
        {
            const float* whb = wh + ko_l * 576 + ci0 * 9;
            const float* hb  = hs + ci0 * 272 + row * 17 + xh;
#pragma unroll 1
            for (int ci = 0; ci < 32; ci++) {
                const float* hp = hb + ci * 272;
                float r0[9], r1[9], r2[9];
#pragma unroll
                for (int i = 0; i < 9; i++) { r0[i] = hp[i]; r1[i] = hp[17 + i]; r2[i] = hp[34 + i]; }
                const float* w9 = whb + ci * 9;
                float w0=w9[0],w1=w9[1],w2=w9[2],w3=w9[3],w4=w9[4],w5=w9[5],w6=w9[6],w7=w9[7],w8=w9[8];
#pragma unroll
                for (int px = 0; px < 7; px++) {
                    ah[px] += w0*r0[px] + w1*r0[px+1] + w2*r0[px+2]
                            + w3*r1[px] + w4*r1[px+1] + w5*r1[px+2]
                            + w6*r2[px] + w7*r2[px+1] + w8*r2[px+2];
                }
            }
        }
        if (half == 1) {
#pragma unroll
            for (int px = 0; px < 7; px++) p0[pidx + px] = ah[px];
        }
        __syncthreads();
        if (half == 0) {
            float* hdst = hstate + ko * PIX + pbase;
            float* fdst = gdst + (n * KC + ko) * PIX + pbase;
#pragma unroll
            for (int px = 0; px < 7; px++) {
                float hh = tanhf(wt[px] + ah[px] + p0[pidx + px]);
                float z  = zreg[px];
                float hn = (1.0f - z) * hh + z * hold[px];
                hdst[px] = hn;
                fdst[px] = hn;
            }
        }

        // ---- group barrier #2 ----
        __threadfence();
        __syncthreads();
        bar_target += 8;
        if (tid == 0) {
            atomicAdd(&g_barrier[grp], 1u);
            while (*((volatile unsigned int*)&g_barrier[grp]) < bar_target) __nanosleep(64);
            __threadfence();
        }
        __syncthreads();
    }
}

// ---------------- softmax over K per pixel + per-(n,k) pixel sums ----------------
__global__ void softmax_kernel()
{
    const int n = blockIdx.x;
    const int p = threadIdx.x;   // 224 threads, 196 active
    const bool act = p < PIX;
    __shared__ float asum_s[KC];
    if (p < KC) asum_s[p] = 0.0f;
    __syncthreads();

    const float* f  = g_fwd + n * KC * PIX + p;
    const float* bd = g_bwd + n * KC * PIX + p;
    float m = -1e30f;
    if (act) {
        for (int k = 0; k < KC; k++) m = fmaxf(m, f[k * PIX] + bd[k * PIX]);
    }
    float ssum = 0.0f;
    if (act) {
        for (int k = 0; k < KC; k++) ssum += expf(f[k * PIX] + bd[k * PIX] - m);
    }
    const float inv = act ? (1.0f / ssum) : 0.0f;
    float* A = g_assign + n * KC * PIX + p;
    for (int k = 0; k < KC; k++) {
        float e = act ? expf(f[k * PIX] + bd[k * PIX] - m) * inv : 0.0f;
        if (act) A[k * PIX] = e;
        float es = e;
#pragma unroll
        for (int off = 16; off; off >>= 1) es += __shfl_down_sync(0xffffffffu, es, off);
        if ((p & 31) == 0) atomicAdd(&asum_s[k], es);
    }
    __syncthreads();
    if (p < KC) g_asum[n * KC + p] = asum_s[p];
}

// ---------------- VLAD einsum ----------------
__global__ void vlad_gemm_kernel()
{
    __shared__ float As[14][65];
    __shared__ float Bs[14][65];
    const int b = blockIdx.y, d0 = blockIdx.x * 64, ch = blockIdx.z;
    const int tid = threadIdx.x;
    const int tx = tid & 15, ty = tid >> 4;

    float acc[4][4];
#pragma unroll
    for (int i = 0; i < 4; i++)
#pragma unroll
        for (int j = 0; j < 4; j++) acc[i][j] = 0.0f;

    for (int f = 0; f < 4; f++) {
        int n = b * 32 + ch * 4 + f;
        const float* Ap = g_assign + n * KC * PIX;
        const float* Xp = g_xr + n * DCH * PIX;
        for (int p0 = 0; p0 < PIX; p0 += 14) {
            for (int i = tid; i < 896; i += 256) {
                int r = i / 14, pp = i - r * 14;
                As[pp][r] = Ap[r * PIX + p0 + pp];
                Bs[pp][r] = Xp[(d0 + r) * PIX + p0 + pp];
            }
            __syncthreads();
#pragma unroll
            for (int pp = 0; pp < 14; pp++) {
                float a[4], x[4];
#pragma unroll
                for (int i = 0; i < 4; i++) a[i] = As[pp][ty * 4 + i];
#pragma unroll
                for (int j = 0; j < 4; j++) x[j] = Bs[pp][tx * 4 + j];
#pragma unroll
                for (int i = 0; i < 4; i++)
#pragma unroll
                    for (int j = 0; j < 4; j++) acc[i][j] += a[i] * x[j];
            }
            __syncthreads();
        }
    }
#pragma unroll
    for (int i = 0; i < 4; i++)
#pragma unroll
        for (int j = 0; j < 4; j++)
            atomicAdd(&g_vlad[(b * KC + ty * 4 + i) * DCH + d0 + tx * 4 + j], acc[i][j]);
}

// ---------------- subtract a-term + intra-row L2 normalize ----------------
__global__ void rownorm_kernel(const float* __restrict__ centers, float* __restrict__ out)
{
    const int k = blockIdx.x, b = blockIdx.y;
    const int tid = threadIdx.x;  // 128
    __shared__ float sred[128];
    __shared__ float s_sh;

    if (tid < 32) {
        float s = g_asum[(b * 32 + tid) * KC + k];
#pragma unroll
        for (int off = 16; off; off >>= 1) s += __shfl_down_sync(0xffffffffu, s, off);
        if (tid == 0) s_sh = s;
    }
    __syncthreads();
    const float s = s_sh;

    float v[4];
    float ssq = 0.0f;
#pragma unroll
    for (int j = 0; j < 4; j++) {
        int d = j * 128 + tid;
        v[j] = g_vlad[(b * KC + k) * DCH + d] - s * centers[k * DCH + d];
        ssq += v[j] * v[j];
    }
    sred[tid] = ssq;
    __syncthreads();
    for (int off = 64; off; off >>= 1) {
        if (tid < off) sred[tid] += sred[tid + off];
        __syncthreads();
    }
    const float scale = 1.0f / fmaxf(sqrtf(sred[0]), 1e-12f);
#pragma unroll
    for (int j = 0; j < 4; j++)
        out[b * KC * DCH + k * DCH + j * 128 + tid] = v[j] * scale;
}

// ---------------- final per-batch L2 normalize ----------------
__global__ void bnorm_kernel(float* __restrict__ out)
{
    const int b = blockIdx.x;
    const int tid = threadIdx.x; // 256
    __shared__ float sred[256];
    float* o = out + b * KC * DCH;
    float ssq = 0.0f;
    for (int i = tid; i < KC * DCH; i += 256) { float v = o[i]; ssq += v * v; }
    sred[tid] = ssq;
    __syncthreads();
    for (int off = 128; off; off >>= 1) {
        if (tid < off) sred[tid] += sred[tid + off];
        __syncthreads();
    }
    const float scale = 1.0f / fmaxf(sqrtf(sred[0]), 1e-12f);
    for (int i = tid; i < KC * DCH; i += 256) o[i] *= scale;
}

// ---------------- host launcher ----------------
extern "C" void kernel_launch(void* const* d_in, const int* in_sizes, int n_in,
                              void* d_out, int out_size)
{
    const float* x       = (const float*)d_in[0];
    const float* redu_w  = (const float*)d_in[1];
    const float* redu_b  = (const float*)d_in[2];
    const float* share_w = (const float*)d_in[3];
    const float* share_b = (const float*)d_in[4];
    const float* U_z     = (const float*)d_in[5];
    const float* U_r     = (const float*)d_in[6];
    const float* U_h     = (const float*)d_in[7];
    const float* centers = (const float*)d_in[8];
    float* out = (float*)d_out;

    const int GRU_SMEM = GRU_SMEM_FLOATS * 4;   // ~134 KB
    cudaFuncSetAttribute(gru_persistent, cudaFuncAttributeMaxDynamicSharedMemorySize, GRU_SMEM);

    void* xr_p;  cudaGetSymbolAddress(&xr_p,  g_xr);
    void* wxb_p; cudaGetSymbolAddress(&wxb_p, g_wxb);

    init_kernel<<<1024, 256>>>();

    // xr = 1x1 reduce conv + bias : GEMM (512 x 1024) @ (1024 x 50176)
    conv1x1_db<128, 8, CIN_, DCH>
        <<<dim3(50176 / 128, DCH / 128), 256>>>(x, redu_w, redu_b, (float*)xr_p);

    // wxb = 1x1 share conv + bias : GEMM (64 x 512) @ (512 x 50176)
    conv1x1_db<64, 4, DCH, KC>
        <<<dim3(50176 / 128, 1), 256>>>((const float*)xr_p, share_w, share_b, (float*)wxb_p);

    // persistent bidirectional GRU: all 32 steps, both directions, one launch
    gru_persistent<<<128, GRU_THREADS, GRU_SMEM>>>(U_z, U_r, U_h);

    softmax_kernel<<<NT, 224>>>();
    vlad_gemm_kernel<<<dim3(8, BATCH, 8), 256>>>();
    rownorm_kernel<<<dim3(KC, BATCH), 128>>>(centers, out);
    bnorm_kernel<<<BATCH, 256>>>(out);
}